// round 3
// baseline (speedup 1.0000x reference)
#include <cuda_runtime.h>

// Delta differential encoding with residual carry + floor quantization.
// x: [B=32, C=2048, T=512] float32, contiguous in T.
// thr = max(threshold[0], 1/64)
// delta[t] = (x[t] - x[t-1]) + r[t-1]   (exact reference arithmetic order)
// y[t]     = delta[t] if |delta[t]| >= thr else 0
// r[t]     = delta[t] - y[t]
// out[t]   = floor(y[t]*64)/64

#define SCALE 64.0f
#define INV_SCALE (1.0f / 64.0f)
#define T_LEN 512
#define N_ROWS (32 * 2048)
#define BATCH 8                    // float4 loads per pipeline stage
#define N_OUTER (T_LEN / 4 / BATCH)  // 16 stages

// Volatile vector load: pins issue order in SASS so prefetch batches really
// go out before the current batch's compute (ptxas otherwise just-in-times
// the loads down to MLP~2, which is what killed rounds 1-2).
__device__ __forceinline__ float4 ldg128v(const float4* p) {
    float4 v;
    asm volatile("ld.global.nc.v4.f32 {%0,%1,%2,%3}, [%4];"
                 : "=f"(v.x), "=f"(v.y), "=f"(v.z), "=f"(v.w)
                 : "l"(p));
    return v;
}

__global__ void __launch_bounds__(64) delta_kernel(
    const float* __restrict__ x,
    const float* __restrict__ thr_in,
    float* __restrict__ out)
{
    int row = blockIdx.x * 64 + threadIdx.x;
    if (row >= N_ROWS) return;

    const float thr = fmaxf(__ldg(thr_in), INV_SCALE);

    const float4* __restrict__ xin  = reinterpret_cast<const float4*>(x   + (size_t)row * T_LEN);
    float4*       __restrict__ yout = reinterpret_cast<float4*>(out + (size_t)row * T_LEN);

    float pre = 0.0f;  // x[t-1]
    float r   = 0.0f;  // residual carry

    float4 buf[2][BATCH];   // register double-buffer (outer loop fully unrolled)

    // Prologue: issue stage 0's loads.
#pragma unroll
    for (int j = 0; j < BATCH; ++j)
        buf[0][j] = ldg128v(xin + j);

#pragma unroll
    for (int o = 0; o < N_OUTER; ++o) {
        const int cur = o & 1;
        const int nxt = cur ^ 1;

        // Prefetch next stage while current stage's carry chain runs.
        if (o + 1 < N_OUTER) {
#pragma unroll
            for (int j = 0; j < BATCH; ++j)
                buf[nxt][j] = ldg128v(xin + (o + 1) * BATCH + j);
        }

        // Process current stage: dx = x[t]-x[t-1] is OFF the carry chain;
        // only d = dx + r -> select -> r is sequential (~21 cyc/elem).
#pragma unroll
        for (int j = 0; j < BATCH; ++j) {
            float4 v = buf[cur][j];
            float4 o4;
            {
                float dx = v.x - pre;  pre = v.x;
                float d  = dx + r;
                float y  = (fabsf(d) >= thr) ? d : 0.0f;
                r = d - y;
                o4.x = floorf(y * SCALE) * INV_SCALE;
            }
            {
                float dx = v.y - pre;  pre = v.y;
                float d  = dx + r;
                float y  = (fabsf(d) >= thr) ? d : 0.0f;
                r = d - y;
                o4.y = floorf(y * SCALE) * INV_SCALE;
            }
            {
                float dx = v.z - pre;  pre = v.z;
                float d  = dx + r;
                float y  = (fabsf(d) >= thr) ? d : 0.0f;
                r = d - y;
                o4.z = floorf(y * SCALE) * INV_SCALE;
            }
            {
                float dx = v.w - pre;  pre = v.w;
                float d  = dx + r;
                float y  = (fabsf(d) >= thr) ? d : 0.0f;
                r = d - y;
                o4.w = floorf(y * SCALE) * INV_SCALE;
            }
            yout[o * BATCH + j] = o4;
        }
    }
}

extern "C" void kernel_launch(void* const* d_in, const int* in_sizes, int n_in,
                              void* d_out, int out_size)
{
    const float* x   = (const float*)d_in[0];
    const float* thr = (const float*)d_in[1];
    float* out       = (float*)d_out;

    const int threads = 64;
    const int blocks  = N_ROWS / threads;   // 1024 blocks
    delta_kernel<<<blocks, threads>>>(x, thr, out);
}

// round 4
// speedup vs baseline: 1.7034x; 1.7034x over previous
#include <cuda_runtime.h>

// Delta differential encoding with residual carry + floor quantization.
// x: [B=32, C=2048, T=512] float32, contiguous in T.
// Strategy: smem-staged tiles. Global accesses fully coalesced (cp.async in,
// cooperative float4 out); the sequential per-row carry chain reads/writes
// conflict-free padded smem rows.

#define SCALE 64.0f
#define INV_SCALE (1.0f / 64.0f)
#define T_LEN 512
#define N_ROWS (32 * 2048)

#define RPB 128            // rows per block == threads per block
#define CHUNK 32           // floats per row per chunk
#define PAD 36             // padded row stride in floats (144B, 16B-aligned, conflict-free)
#define NCHUNK (T_LEN / CHUNK)       // 16
#define F4_PER_ROW (CHUNK / 4)       // 8
#define F4_PER_THREAD F4_PER_ROW     // 1024 float4 / 128 threads

#define SMEM_FLOATS (3 * RPB * PAD)  // in0 + in1 + out
#define SMEM_BYTES (SMEM_FLOATS * 4) // 55296

__global__ void __launch_bounds__(RPB) delta_kernel(
    const float* __restrict__ x,
    const float* __restrict__ thr_in,
    float* __restrict__ out)
{
    extern __shared__ float smem[];
    float* sin0 = smem;
    float* sin1 = smem + RPB * PAD;
    float* sout = smem + 2 * RPB * PAD;

    const int tid = threadIdx.x;
    const size_t rowbase = (size_t)blockIdx.x * RPB;
    const float* gx = x + rowbase * T_LEN;
    float* gy = out + rowbase * T_LEN;

    const float thr = fmaxf(__ldg(thr_in), INV_SCALE);

    // ---- async load of one chunk (coalesced: consecutive threads ->
    //      consecutive float4; warp covers 4 contiguous 128B lines) ----
    auto issue_chunk = [&](float* sbuf, int k) {
        const float* gsrc = gx + (size_t)k * CHUNK;
#pragma unroll
        for (int i = 0; i < F4_PER_THREAD; ++i) {
            int f = tid + RPB * i;          // flat float4 index 0..1023
            int row = f >> 3;               // f / 8
            int t4  = f & 7;                // f % 8
            const float* src = gsrc + (size_t)row * T_LEN + t4 * 4;
            unsigned saddr = (unsigned)__cvta_generic_to_shared(sbuf + row * PAD + t4 * 4);
            asm volatile("cp.async.cg.shared.global [%0], [%1], 16;"
                         :: "r"(saddr), "l"(src));
        }
        asm volatile("cp.async.commit_group;");
    };

    issue_chunk(sin0, 0);

    float pre = 0.0f;  // x[t-1]
    float r   = 0.0f;  // residual carry

#pragma unroll 1
    for (int k = 0; k < NCHUNK; ++k) {
        float* sin = (k & 1) ? sin1 : sin0;

        // Prefetch next chunk into the other buffer, then wait for current.
        if (k + 1 < NCHUNK) {
            issue_chunk((k & 1) ? sin0 : sin1, k + 1);
            asm volatile("cp.async.wait_group 1;");
        } else {
            asm volatile("cp.async.wait_group 0;");
        }
        __syncthreads();   // current chunk visible to all; also fences prior sout reads

        // ---- sequential carry chain on own row (conflict-free smem) ----
        const float* myrow = sin  + tid * PAD;
        float*       orow  = sout + tid * PAD;
#pragma unroll
        for (int j = 0; j < F4_PER_ROW; ++j) {
            float4 v = *reinterpret_cast<const float4*>(myrow + 4 * j);
            float4 o4;
            {
                float dx = v.x - pre;  pre = v.x;
                float d  = dx + r;
                float y  = (fabsf(d) >= thr) ? d : 0.0f;
                r = d - y;
                o4.x = floorf(y * SCALE) * INV_SCALE;
            }
            {
                float dx = v.y - pre;  pre = v.y;
                float d  = dx + r;
                float y  = (fabsf(d) >= thr) ? d : 0.0f;
                r = d - y;
                o4.y = floorf(y * SCALE) * INV_SCALE;
            }
            {
                float dx = v.z - pre;  pre = v.z;
                float d  = dx + r;
                float y  = (fabsf(d) >= thr) ? d : 0.0f;
                r = d - y;
                o4.z = floorf(y * SCALE) * INV_SCALE;
            }
            {
                float dx = v.w - pre;  pre = v.w;
                float d  = dx + r;
                float y  = (fabsf(d) >= thr) ? d : 0.0f;
                r = d - y;
                o4.w = floorf(y * SCALE) * INV_SCALE;
            }
            *reinterpret_cast<float4*>(orow + 4 * j) = o4;
        }
        __syncthreads();   // sout complete before cooperative store

        // ---- cooperative coalesced store of this chunk ----
        float* gdst = gy + (size_t)k * CHUNK;
#pragma unroll
        for (int i = 0; i < F4_PER_THREAD; ++i) {
            int f = tid + RPB * i;
            int row = f >> 3;
            int t4  = f & 7;
            *reinterpret_cast<float4*>(gdst + (size_t)row * T_LEN + t4 * 4) =
                *reinterpret_cast<const float4*>(sout + row * PAD + t4 * 4);
        }
    }
}

extern "C" void kernel_launch(void* const* d_in, const int* in_sizes, int n_in,
                              void* d_out, int out_size)
{
    const float* x   = (const float*)d_in[0];
    const float* thr = (const float*)d_in[1];
    float* out       = (float*)d_out;

    cudaFuncSetAttribute(delta_kernel,
                         cudaFuncAttributeMaxDynamicSharedMemorySize, SMEM_BYTES);

    const int blocks = N_ROWS / RPB;   // 512
    delta_kernel<<<blocks, RPB, SMEM_BYTES>>>(x, thr, out);
}

// round 5
// speedup vs baseline: 1.7292x; 1.0152x over previous
#include <cuda_runtime.h>

// Delta differential encoding with residual carry + floor quantization.
// x: [B=32, C=2048, T=512] float32, contiguous in T.
// Warp-private smem staging: each warp stages its own 32 rows, so all
// synchronization is __syncwarp (no block barriers). Global access fully
// coalesced; carry chain shortened to FADD->FSETP->FSEL per element.

#define SCALE 64.0f
#define INV_SCALE (1.0f / 64.0f)
#define T_LEN 512
#define N_ROWS (32 * 2048)

#define RPW 32             // rows per warp (one per lane)
#define WARPS 4
#define RPB (RPW * WARPS)  // 128 threads/block
#define CHUNK 32           // floats per row per chunk (= one 128B line)
#define PAD 36             // padded row stride in floats (conflict-free, 16B aligned)
#define NCHUNK (T_LEN / CHUNK)   // 16
#define F4_PER_LANE 8            // 32 rows * 8 float4 / 32 lanes

#define WARP_REGION (3 * RPW * PAD)          // in0 + in1 + out, floats
#define SMEM_BYTES (WARPS * WARP_REGION * 4) // 55296

__global__ void __launch_bounds__(RPB) delta_kernel(
    const float* __restrict__ x,
    const float* __restrict__ thr_in,
    float* __restrict__ out)
{
    extern __shared__ float smem[];

    const int tid  = threadIdx.x;
    const int warp = tid >> 5;
    const int lane = tid & 31;

    float* wbase = smem + warp * WARP_REGION;
    float* sin0 = wbase;
    float* sin1 = wbase + RPW * PAD;
    float* sout = wbase + 2 * RPW * PAD;

    // This warp's 32 rows in global memory.
    const size_t rowbase = (size_t)blockIdx.x * RPB + warp * RPW;
    const float* gx = x   + rowbase * T_LEN;
    float*       gy = out + rowbase * T_LEN;

    const float thr = fmaxf(__ldg(thr_in), INV_SCALE);

    // Coalesced async load of one chunk into this warp's buffer:
    // 8 consecutive lanes cover one row's 128B line.
    auto issue_chunk = [&](float* sbuf, int k) {
        const float* gsrc = gx + (size_t)k * CHUNK;
#pragma unroll
        for (int i = 0; i < F4_PER_LANE; ++i) {
            int f   = lane + 32 * i;    // 0..255
            int row = f >> 3;           // 0..31
            int t4  = f & 7;            // 0..7
            const float* src = gsrc + (size_t)row * T_LEN + t4 * 4;
            unsigned saddr = (unsigned)__cvta_generic_to_shared(sbuf + row * PAD + t4 * 4);
            asm volatile("cp.async.cg.shared.global [%0], [%1], 16;"
                         :: "r"(saddr), "l"(src));
        }
        asm volatile("cp.async.commit_group;");
    };

    issue_chunk(sin0, 0);

    float pre = 0.0f;  // x[t-1]
    float r   = 0.0f;  // residual carry

#pragma unroll 1
    for (int k = 0; k < NCHUNK; ++k) {
        float* sin = (k & 1) ? sin1 : sin0;

        if (k + 1 < NCHUNK) {
            issue_chunk((k & 1) ? sin0 : sin1, k + 1);
            asm volatile("cp.async.wait_group 1;");
        } else {
            asm volatile("cp.async.wait_group 0;");
        }
        __syncwarp();   // all lanes' copies of current chunk visible warp-wide

        // Sequential carry chain on own row (conflict-free padded smem).
        // r[t] = (|d|>=thr) ? 0 : d  -- parallel select, no dependent subtract.
        const float* myrow = sin  + lane * PAD;
        float*       orow  = sout + lane * PAD;
#pragma unroll
        for (int j = 0; j < CHUNK / 4; ++j) {
            float4 v = *reinterpret_cast<const float4*>(myrow + 4 * j);
            float4 o4;
            {
                float dx = v.x - pre;  pre = v.x;
                float d  = dx + r;
                bool  c  = fabsf(d) >= thr;
                float y  = c ? d : 0.0f;
                r        = c ? 0.0f : d;
                o4.x = floorf(y * SCALE) * INV_SCALE;
            }
            {
                float dx = v.y - pre;  pre = v.y;
                float d  = dx + r;
                bool  c  = fabsf(d) >= thr;
                float y  = c ? d : 0.0f;
                r        = c ? 0.0f : d;
                o4.y = floorf(y * SCALE) * INV_SCALE;
            }
            {
                float dx = v.z - pre;  pre = v.z;
                float d  = dx + r;
                bool  c  = fabsf(d) >= thr;
                float y  = c ? d : 0.0f;
                r        = c ? 0.0f : d;
                o4.z = floorf(y * SCALE) * INV_SCALE;
            }
            {
                float dx = v.w - pre;  pre = v.w;
                float d  = dx + r;
                bool  c  = fabsf(d) >= thr;
                float y  = c ? d : 0.0f;
                r        = c ? 0.0f : d;
                o4.w = floorf(y * SCALE) * INV_SCALE;
            }
            *reinterpret_cast<float4*>(orow + 4 * j) = o4;
        }
        __syncwarp();   // sout complete before cooperative store

        // Coalesced store of this chunk.
        float* gdst = gy + (size_t)k * CHUNK;
#pragma unroll
        for (int i = 0; i < F4_PER_LANE; ++i) {
            int f   = lane + 32 * i;
            int row = f >> 3;
            int t4  = f & 7;
            *reinterpret_cast<float4*>(gdst + (size_t)row * T_LEN + t4 * 4) =
                *reinterpret_cast<const float4*>(sout + row * PAD + t4 * 4);
        }
        __syncwarp();   // store-reads of sout done before next iter overwrites
    }
}

extern "C" void kernel_launch(void* const* d_in, const int* in_sizes, int n_in,
                              void* d_out, int out_size)
{
    const float* x   = (const float*)d_in[0];
    const float* thr = (const float*)d_in[1];
    float* out       = (float*)d_out;

    cudaFuncSetAttribute(delta_kernel,
                         cudaFuncAttributeMaxDynamicSharedMemorySize, SMEM_BYTES);

    const int blocks = N_ROWS / RPB;   // 512
    delta_kernel<<<blocks, RPB, SMEM_BYTES>>>(x, thr, out);
}

// round 6
// speedup vs baseline: 1.7568x; 1.0160x over previous
#include <cuda_runtime.h>

// Delta differential encoding with residual carry + floor quantization.
// x: [B=32, C=2048, T=512] float32, contiguous in T.
// Warp-private smem staging, depth-3 cp.async pipeline (2 chunks in flight),
// in-place output (compute overwrites the input buffer), speculative carry
// chain (8 cyc/element critical path).

#define SCALE 64.0f
#define INV_SCALE (1.0f / 64.0f)
#define T_LEN 512
#define N_ROWS (32 * 2048)

#define RPW 32             // rows per warp (one per lane)
#define WARPS 4
#define RPB (RPW * WARPS)  // 128 threads/block
#define CHUNK 32           // floats per row per chunk (= one 128B line)
#define PAD 36             // padded row stride in floats (conflict-free, 16B aligned)
#define NCHUNK (T_LEN / CHUNK)   // 16
#define F4_PER_LANE 8            // 32 rows * 8 float4 / 32 lanes
#define DEPTH 3

#define BUF_FLOATS (RPW * PAD)               // one buffer
#define WARP_REGION (DEPTH * BUF_FLOATS)     // floats per warp
#define SMEM_BYTES (WARPS * WARP_REGION * 4) // 55296

__global__ void __launch_bounds__(RPB) delta_kernel(
    const float* __restrict__ x,
    const float* __restrict__ thr_in,
    float* __restrict__ out)
{
    extern __shared__ float smem[];

    const int tid  = threadIdx.x;
    const int warp = tid >> 5;
    const int lane = tid & 31;

    float* wbase = smem + warp * WARP_REGION;
    float* bufs[DEPTH] = { wbase, wbase + BUF_FLOATS, wbase + 2 * BUF_FLOATS };

    const size_t rowbase = (size_t)blockIdx.x * RPB + warp * RPW;
    const float* gx = x   + rowbase * T_LEN;
    float*       gy = out + rowbase * T_LEN;

    const float thr = fmaxf(__ldg(thr_in), INV_SCALE);

    // Coalesced async load of one chunk: 8 consecutive lanes cover one row's 128B line.
    auto issue_chunk = [&](float* sbuf, int k) {
        const float* gsrc = gx + (size_t)k * CHUNK;
#pragma unroll
        for (int i = 0; i < F4_PER_LANE; ++i) {
            int f   = lane + 32 * i;    // 0..255
            int row = f >> 3;
            int t4  = f & 7;
            const float* src = gsrc + (size_t)row * T_LEN + t4 * 4;
            unsigned saddr = (unsigned)__cvta_generic_to_shared(sbuf + row * PAD + t4 * 4);
            asm volatile("cp.async.cg.shared.global [%0], [%1], 16;"
                         :: "r"(saddr), "l"(src));
        }
        asm volatile("cp.async.commit_group;");
    };

    // Prologue: fill two stages.
    issue_chunk(bufs[0], 0);
    issue_chunk(bufs[1], 1);

    float pre = 0.0f;  // x[t-1] at chunk boundary
    float r   = 0.0f;  // residual carry at chunk boundary

#pragma unroll 1
    for (int k = 0; k < NCHUNK; ++k) {
        float* sbuf = bufs[k % DEPTH];

        if (k + 2 < NCHUNK) {
            issue_chunk(bufs[(k + 2) % DEPTH], k + 2);
            asm volatile("cp.async.wait_group 2;");
        } else if (k + 1 < NCHUNK) {
            asm volatile("cp.async.wait_group 1;");
        } else {
            asm volatile("cp.async.wait_group 0;");
        }
        __syncwarp();   // chunk k visible warp-wide

        // ---- load own row into registers, compute dx off-chain ----
        float* myrow = sbuf + lane * PAD;
        float a[CHUNK];
#pragma unroll
        for (int j4 = 0; j4 < CHUNK / 4; ++j4) {
            float4 v = *reinterpret_cast<const float4*>(myrow + 4 * j4);
            a[4 * j4 + 0] = v.x;
            a[4 * j4 + 1] = v.y;
            a[4 * j4 + 2] = v.z;
            a[4 * j4 + 3] = v.w;
        }
        float dx[CHUNK];
        dx[0] = a[0] - pre;
#pragma unroll
        for (int j = 1; j < CHUNK; ++j) dx[j] = a[j] - a[j - 1];
        pre = a[CHUNK - 1];

        // ---- speculative carry chain: 8 cyc/element critical path ----
        // d = delta of element j; d_next = keep ? dx[j+1] : dx[j+1] + d.
        float d = dx[0] + r;
        float o4s[CHUNK];
#pragma unroll
        for (int j = 0; j < CHUNK; ++j) {
            bool  keep = fabsf(d) >= thr;
            float y    = keep ? d : 0.0f;
            o4s[j]     = floorf(y * SCALE) * INV_SCALE;
            if (j + 1 < CHUNK) {
                float dc = dx[j + 1] + d;       // starts as soon as d resolves
                d = keep ? dx[j + 1] : dc;      // FSEL, pred-as-data
            } else {
                r = keep ? 0.0f : d;
            }
        }

        // ---- write results back in place ----
#pragma unroll
        for (int j4 = 0; j4 < CHUNK / 4; ++j4) {
            float4 o4;
            o4.x = o4s[4 * j4 + 0];
            o4.y = o4s[4 * j4 + 1];
            o4.z = o4s[4 * j4 + 2];
            o4.w = o4s[4 * j4 + 3];
            *reinterpret_cast<float4*>(myrow + 4 * j4) = o4;
        }
        __syncwarp();   // all rows' outputs in place before cooperative store

        // ---- coalesced cooperative store of this chunk ----
        float* gdst = gy + (size_t)k * CHUNK;
#pragma unroll
        for (int i = 0; i < F4_PER_LANE; ++i) {
            int f   = lane + 32 * i;
            int row = f >> 3;
            int t4  = f & 7;
            *reinterpret_cast<float4*>(gdst + (size_t)row * T_LEN + t4 * 4) =
                *reinterpret_cast<const float4*>(sbuf + row * PAD + t4 * 4);
        }
        __syncwarp();   // store reads done before chunk k+3's cp.async reuses sbuf
    }
}

extern "C" void kernel_launch(void* const* d_in, const int* in_sizes, int n_in,
                              void* d_out, int out_size)
{
    const float* x   = (const float*)d_in[0];
    const float* thr = (const float*)d_in[1];
    float* out       = (float*)d_out;

    cudaFuncSetAttribute(delta_kernel,
                         cudaFuncAttributeMaxDynamicSharedMemorySize, SMEM_BYTES);

    const int blocks = N_ROWS / RPB;   // 512
    delta_kernel<<<blocks, RPB, SMEM_BYTES>>>(x, thr, out);
}

// round 7
// speedup vs baseline: 1.8332x; 1.0435x over previous
#include <cuda_runtime.h>

// Delta differential encoding with residual carry + floor quantization.
// x: [B=32, C=2048, T=512] float32, contiguous in T.
// One warp per block (32 rows/block) so the 2048 warps spread across 148 SMs
// with ~1% imbalance (512x4-warp blocks gave 4-vs-3 blocks/SM = ~30% tail).
// Warp-private smem staging, depth-3 cp.async pipeline, in-place output,
// speculative carry chain.

#define SCALE 64.0f
#define INV_SCALE (1.0f / 64.0f)
#define T_LEN 512
#define N_ROWS (32 * 2048)

#define RPW 32             // rows per warp (one per lane)
#define RPB 32             // 1 warp per block
#define CHUNK 32           // floats per row per chunk (= one 128B line)
#define PAD 36             // padded row stride in floats (conflict-free, 16B aligned)
#define NCHUNK (T_LEN / CHUNK)   // 16
#define F4_PER_LANE 8            // 32 rows * 8 float4 / 32 lanes
#define DEPTH 3

#define BUF_FLOATS (RPW * PAD)           // one buffer
#define SMEM_FLOATS (DEPTH * BUF_FLOATS)
#define SMEM_BYTES (SMEM_FLOATS * 4)     // 13824 B/block -> 14 blocks/SM fits 193KB

__global__ void __launch_bounds__(RPB) delta_kernel(
    const float* __restrict__ x,
    const float* __restrict__ thr_in,
    float* __restrict__ out)
{
    extern __shared__ float smem[];

    const int lane = threadIdx.x & 31;

    float* bufs[DEPTH] = { smem, smem + BUF_FLOATS, smem + 2 * BUF_FLOATS };

    const size_t rowbase = (size_t)blockIdx.x * RPW;
    const float* gx = x   + rowbase * T_LEN;
    float*       gy = out + rowbase * T_LEN;

    const float thr = fmaxf(__ldg(thr_in), INV_SCALE);

    // Coalesced async load of one chunk: 8 consecutive lanes cover one row's 128B line.
    auto issue_chunk = [&](float* sbuf, int k) {
        const float* gsrc = gx + (size_t)k * CHUNK;
#pragma unroll
        for (int i = 0; i < F4_PER_LANE; ++i) {
            int f   = lane + 32 * i;    // 0..255
            int row = f >> 3;
            int t4  = f & 7;
            const float* src = gsrc + (size_t)row * T_LEN + t4 * 4;
            unsigned saddr = (unsigned)__cvta_generic_to_shared(sbuf + row * PAD + t4 * 4);
            asm volatile("cp.async.cg.shared.global [%0], [%1], 16;"
                         :: "r"(saddr), "l"(src));
        }
        asm volatile("cp.async.commit_group;");
    };

    // Prologue: fill two stages.
    issue_chunk(bufs[0], 0);
    issue_chunk(bufs[1], 1);

    float pre = 0.0f;  // x[t-1] at chunk boundary
    float r   = 0.0f;  // residual carry at chunk boundary

#pragma unroll 1
    for (int k = 0; k < NCHUNK; ++k) {
        float* sbuf = bufs[k % DEPTH];

        if (k + 2 < NCHUNK) {
            issue_chunk(bufs[(k + 2) % DEPTH], k + 2);
            asm volatile("cp.async.wait_group 2;");
        } else if (k + 1 < NCHUNK) {
            asm volatile("cp.async.wait_group 1;");
        } else {
            asm volatile("cp.async.wait_group 0;");
        }
        __syncwarp();   // chunk k visible warp-wide

        // ---- load own row into registers, compute dx off-chain ----
        float* myrow = sbuf + lane * PAD;
        float a[CHUNK];
#pragma unroll
        for (int j4 = 0; j4 < CHUNK / 4; ++j4) {
            float4 v = *reinterpret_cast<const float4*>(myrow + 4 * j4);
            a[4 * j4 + 0] = v.x;
            a[4 * j4 + 1] = v.y;
            a[4 * j4 + 2] = v.z;
            a[4 * j4 + 3] = v.w;
        }
        float dx[CHUNK];
        dx[0] = a[0] - pre;
#pragma unroll
        for (int j = 1; j < CHUNK; ++j) dx[j] = a[j] - a[j - 1];
        pre = a[CHUNK - 1];

        // ---- speculative carry chain: ~8 cyc/element critical path ----
        float d = dx[0] + r;
        float o4s[CHUNK];
#pragma unroll
        for (int j = 0; j < CHUNK; ++j) {
            bool  keep = fabsf(d) >= thr;
            float y    = keep ? d : 0.0f;
            o4s[j]     = floorf(y * SCALE) * INV_SCALE;
            if (j + 1 < CHUNK) {
                float dc = dx[j + 1] + d;       // starts as soon as d resolves
                d = keep ? dx[j + 1] : dc;      // FSEL, pred-as-data
            } else {
                r = keep ? 0.0f : d;
            }
        }

        // ---- write results back in place ----
#pragma unroll
        for (int j4 = 0; j4 < CHUNK / 4; ++j4) {
            float4 o4;
            o4.x = o4s[4 * j4 + 0];
            o4.y = o4s[4 * j4 + 1];
            o4.z = o4s[4 * j4 + 2];
            o4.w = o4s[4 * j4 + 3];
            *reinterpret_cast<float4*>(myrow + 4 * j4) = o4;
        }
        __syncwarp();   // all rows' outputs in place before cooperative store

        // ---- coalesced cooperative store of this chunk ----
        float* gdst = gy + (size_t)k * CHUNK;
#pragma unroll
        for (int i = 0; i < F4_PER_LANE; ++i) {
            int f   = lane + 32 * i;
            int row = f >> 3;
            int t4  = f & 7;
            *reinterpret_cast<float4*>(gdst + (size_t)row * T_LEN + t4 * 4) =
                *reinterpret_cast<const float4*>(sbuf + row * PAD + t4 * 4);
        }
        __syncwarp();   // store reads done before chunk k+3's cp.async reuses sbuf
    }
}

extern "C" void kernel_launch(void* const* d_in, const int* in_sizes, int n_in,
                              void* d_out, int out_size)
{
    const float* x   = (const float*)d_in[0];
    const float* thr = (const float*)d_in[1];
    float* out       = (float*)d_out;

    const int blocks = N_ROWS / RPW;   // 2048 one-warp blocks
    delta_kernel<<<blocks, RPB, SMEM_BYTES>>>(x, thr, out);
}